// round 3
// baseline (speedup 1.0000x reference)
#include <cuda_runtime.h>
#include <cuda_bf16.h>

// PPO loss: reverse GAE scan + reverse value-target scan + fused reductions.
// Decay factors (0.9405, 0.99) make the reverse recurrences effectively local:
// 0.99^2048 ~ 1.2e-9, so each block handles an independent 8192-element output
// chunk with a 2048-element read-ahead halo. Single pass, no cross-block deps.

#define PPO_EPS    0.2f
#define PPO_GAMMA  0.99f
#define PPO_A1     (0.99f * 0.95f)   // gamma * lambda
#define PPO_C1     0.5f
#define PPO_C2     0.01f

#define THREADS    512
#define SEG        20                      // elements per thread (serial scan)
#define ELEMS      (THREADS * SEG)         // 10240 = chunk + halo
#define OUT_CHUNK  8192                    // outputs per block
#define HALO       (ELEMS - OUT_CHUNK)     // 2048 read-ahead window

// Padded SMEM layout: one pad word per SEG elements. Thread j's segment starts
// at word 21*j (gcd(21,32)=1 -> conflict-free strided access). NOTE: within a
// 21-word group only offsets 0..19 are data; offset 20 is PAD (never written),
// so "element after segment end" lives at baseP + 21, NOT baseP + 20.
#define R_PAD  10752   // >= pi(ELEMS-1)+1 = 10751
#define V_PAD  10756   // >= pi(ELEMS)+1  = 10753 (v needs one extra trailing elem)

__device__ float g_partials[4096];

__device__ __forceinline__ int pi(int i) { return i + i / SEG; }

// Compile-time double-precision pow (host+device so it's usable in kernels
// without --expt-relaxed-constexpr; folds to an immediate either way).
__host__ __device__ constexpr double dpow(double b, int n) {
    double r = 1.0;
    for (int i = 0; i < n; ++i) r *= b;
    return r;
}
#define FG0 ((float)dpow((double)PPO_A1,    SEG))   // a1^20
#define FV0 ((float)dpow((double)PPO_GAMMA, SEG))   // gamma^20

__global__ __launch_bounds__(THREADS, 2)
void ppo_main(const float* __restrict__ probs,
              const float* __restrict__ probs_old,
              const float* __restrict__ rewards,
              const float* __restrict__ values,
              int T)
{
    extern __shared__ float sm[];
    float* r_s = sm;                    // [R_PAD], later overwritten with advantages
    float* v_s = sm + R_PAD;            // [V_PAD]
    float* sg  = sm + R_PAD + V_PAD;    // [THREADS] scan / reduce scratch (gae)
    float* sv  = sg + THREADS;          // [THREADS] scan scratch (value target)

    const int tid = threadIdx.x;
    const long long s = (long long)blockIdx.x * OUT_CHUNK;

    // ---- Stage rewards/values (chunk + halo + 1 trailing value) coalesced ----
    for (int i = tid; i <= ELEMS; i += THREADS) {
        long long gi = s + i;
        float rv = 0.0f, vv = 0.0f;
        if (gi < (long long)T) {
            vv = values[gi];
            if (i < ELEMS) rv = rewards[gi];
        }
        if (i < ELEMS) r_s[pi(i)] = rv;
        v_s[pi(i)] = vv;
    }
    __syncthreads();

    // ---- Per-thread local reverse-scan aggregates over its SEG elements ----
    const int baseP = 21 * tid;  // padded start of this thread's segment
    float Lg = 0.0f, Lv = 0.0f;
    {
        float vNext = v_s[baseP + 21];  // first element of NEXT segment (pad-aware)
        #pragma unroll
        for (int i = SEG - 1; i >= 0; --i) {
            float r = r_s[baseP + i];
            float v = v_s[baseP + i];
            float delta = r - v + PPO_GAMMA * vNext;
            Lg = fmaf(PPO_A1,    Lg, delta);
            Lv = fmaf(PPO_GAMMA, Lv, r);
            vNext = v;
        }
    }
    sg[tid] = Lg;
    sv[tid] = Lv;
    __syncthreads();

    // ---- Block-level reverse inclusive scan (Hillis-Steele, uniform factors) ----
    float Fg = FG0;
    float Fv = FV0;
    float vg = Lg, vvt = Lv;
    #pragma unroll
    for (int off = 1; off < THREADS; off <<= 1) {
        float ag = 0.0f, av = 0.0f;
        if (tid + off < THREADS) { ag = sg[tid + off]; av = sv[tid + off]; }
        __syncthreads();
        vg  = fmaf(Fg, ag, vg);
        vvt = fmaf(Fv, av, vvt);
        sg[tid] = vg;
        sv[tid] = vvt;
        Fg *= Fg; Fv *= Fv;
        __syncthreads();
    }
    float Eg = (tid + 1 < THREADS) ? sg[tid + 1] : 0.0f;  // carry into segment end
    float Ev = (tid + 1 < THREADS) ? sv[tid + 1] : 0.0f;
    __syncthreads();  // protect sg/sv before reduction reuse

    // ---- Serial recompute with carry: value loss + advantages (overwrite r_s) ----
    const int baseL = tid * SEG;
    float s_vl = 0.0f;
    {
        float g = Eg, V = Ev;
        float vNext = v_s[baseP + 21];  // pad-aware next-segment element
        #pragma unroll
        for (int i = SEG - 1; i >= 0; --i) {
            float r = r_s[baseP + i];
            float v = v_s[baseP + i];
            float delta = r - v + PPO_GAMMA * vNext;
            g = fmaf(PPO_A1,    g, delta);
            V = fmaf(PPO_GAMMA, V, r);
            vNext = v;
            if (baseL + i < OUT_CHUNK) {
                float d = v - V;
                s_vl = fmaf(d, d, s_vl);
                r_s[baseP + i] = g;  // advantage, in place of reward
            }
        }
    }
    __syncthreads();

    // ---- Coalesced pass: clip loss + entropy using staged advantages ----
    int rem = OUT_CHUNK;
    if ((long long)T - s < (long long)OUT_CHUNK) rem = (int)((long long)T - s);
    float s_clip = 0.0f, s_ent = 0.0f;
    for (int li = tid; li < rem; li += THREADS) {
        long long gi = s + li;
        float p   = probs[gi];
        float po  = probs_old[gi];
        float adv = r_s[pi(li)];
        float ratio = p / po;
        float cl = fminf(fmaxf(ratio, 1.0f - PPO_EPS), 1.0f + PPO_EPS);
        s_clip += fminf(ratio * adv, cl * adv);
        s_ent   = fmaf(p, __logf(p + 1e-5f), s_ent);
    }

    // total = clip_loss + C1*value_loss + C2*entropy_loss
    //       = -s_clip + C1*s_vl - C2*s_ent
    float part = -s_clip + PPO_C1 * s_vl - PPO_C2 * s_ent;

    // ---- Deterministic block tree reduction ----
    sg[tid] = part;
    __syncthreads();
    #pragma unroll
    for (int off = THREADS / 2; off > 0; off >>= 1) {
        if (tid < off) sg[tid] += sg[tid + off];
        __syncthreads();
    }
    if (tid == 0) g_partials[blockIdx.x] = sg[0];
}

__global__ void ppo_reduce(float* __restrict__ out, int nblocks)
{
    __shared__ float sd[1024];
    int tid = threadIdx.x;
    float x = 0.0f;
    for (int i = tid; i < nblocks; i += 1024) x += g_partials[i];
    sd[tid] = x;
    __syncthreads();
    #pragma unroll
    for (int off = 512; off > 0; off >>= 1) {
        if (tid < off) sd[tid] += sd[tid + off];
        __syncthreads();
    }
    if (tid == 0) out[0] = sd[0];
}

extern "C" void kernel_launch(void* const* d_in, const int* in_sizes, int n_in,
                              void* d_out, int out_size)
{
    const float* probs     = (const float*)d_in[0];
    const float* probs_old = (const float*)d_in[1];
    const float* rewards   = (const float*)d_in[2];
    const float* values    = (const float*)d_in[3];
    int T = in_sizes[0];

    int nblocks = (T + OUT_CHUNK - 1) / OUT_CHUNK;
    if (nblocks > 4096) nblocks = 4096;  // g_partials capacity (T=2^23 -> 1024)

    size_t smem_bytes = (size_t)(R_PAD + V_PAD + 2 * THREADS) * sizeof(float);
    cudaFuncSetAttribute(ppo_main, cudaFuncAttributeMaxDynamicSharedMemorySize,
                         (int)smem_bytes);

    ppo_main<<<nblocks, THREADS, smem_bytes>>>(probs, probs_old, rewards, values, T);
    ppo_reduce<<<1, 1024>>>((float*)d_out, nblocks);
}

// round 4
// speedup vs baseline: 2.4706x; 2.4706x over previous
#include <cuda_runtime.h>
#include <cuda_bf16.h>

// PPO loss, single fused kernel.
// Reverse GAE + value-target recurrences are effectively local (0.99^2048 ~ 1.2e-9):
// each block independently produces OUT_CHUNK outputs from a register-resident
// segment scan with a 2048-element halo. r/v loaded as float4 directly to registers
// (80B/thread stride, 100% line utilization); advantages parked in SMEM for the
// coalesced probs pass; final scalar via last-block reduction (no 2nd kernel).

#define PPO_EPS    0.2f
#define PPO_GAMMA  0.99f
#define PPO_A1     (0.99f * 0.95f)   // gamma * lambda
#define PPO_C1     0.5f
#define PPO_C2     0.01f

#define THREADS    512
#define SEG        20                     // elements per thread
#define ELEMS      (THREADS * SEG)        // 10240 = chunk + halo
#define OUT_CHUNK  8192                   // outputs per block (halo = 2048)

// advantages in padded layout pi(i)=i+i/SEG (stride-21 per thread, conflict-free)
#define ADV_WORDS  8608                   // > pi(OUT_CHUNK-1) = 8600

__device__ float g_partials[4096];
__device__ unsigned int g_count = 0;

__host__ __device__ constexpr double dpow(double b, int n) {
    double r = 1.0;
    for (int i = 0; i < n; ++i) r *= b;
    return r;
}
#define FG0 ((float)dpow((double)PPO_A1,    SEG))   // a1^20
#define FV0 ((float)dpow((double)PPO_GAMMA, SEG))   // gamma^20

__global__ __launch_bounds__(THREADS, 2)
void ppo_fused(const float* __restrict__ probs,
               const float* __restrict__ probs_old,
               const float* __restrict__ rewards,
               const float* __restrict__ values,
               float* __restrict__ out,
               int T)
{
    __shared__ float adv[ADV_WORDS];
    __shared__ float sg[THREADS];
    __shared__ float sv[THREADS];
    __shared__ unsigned int s_last;

    const int tid = threadIdx.x;
    const long long s = (long long)blockIdx.x * OUT_CHUNK;
    const long long gbase = s + (long long)tid * SEG;

    // ---- Load this thread's segment (20 r, 20 v, 1 lookahead v) into registers ----
    float r[SEG], v[SEG], vNext;
    if (gbase + SEG < (long long)T) {           // fast path: fully in range
        #pragma unroll
        for (int k = 0; k < SEG / 4; ++k) {
            float4 r4 = *reinterpret_cast<const float4*>(rewards + gbase + 4 * k);
            float4 v4 = *reinterpret_cast<const float4*>(values  + gbase + 4 * k);
            r[4*k+0] = r4.x; r[4*k+1] = r4.y; r[4*k+2] = r4.z; r[4*k+3] = r4.w;
            v[4*k+0] = v4.x; v[4*k+1] = v4.y; v[4*k+2] = v4.z; v[4*k+3] = v4.w;
        }
        vNext = values[gbase + SEG];
    } else {                                    // tail block halo: guarded scalar
        #pragma unroll
        for (int i = 0; i < SEG; ++i) {
            long long gi = gbase + i;
            bool ok = gi < (long long)T;
            r[i] = ok ? rewards[gi] : 0.0f;
            v[i] = ok ? values[gi]  : 0.0f;
        }
        vNext = 0.0f;                           // gbase+SEG >= T here
    }

    // ---- Per-thread reverse aggregates over the segment ----
    float Lg = 0.0f, Lv = 0.0f;
    {
        float vn = vNext;
        #pragma unroll
        for (int i = SEG - 1; i >= 0; --i) {
            float delta = r[i] - v[i] + PPO_GAMMA * vn;
            Lg = fmaf(PPO_A1,    Lg, delta);
            Lv = fmaf(PPO_GAMMA, Lv, r[i]);
            vn = v[i];
        }
    }
    sg[tid] = Lg;
    sv[tid] = Lv;
    __syncthreads();

    // ---- Block-level reverse inclusive scan (Hillis-Steele, uniform factors) ----
    float Fg = FG0, Fv = FV0;
    float vg = Lg, vvt = Lv;
    #pragma unroll
    for (int off = 1; off < THREADS; off <<= 1) {
        float ag = 0.0f, av = 0.0f;
        if (tid + off < THREADS) { ag = sg[tid + off]; av = sv[tid + off]; }
        __syncthreads();
        vg  = fmaf(Fg, ag, vg);
        vvt = fmaf(Fv, av, vvt);
        sg[tid] = vg;
        sv[tid] = vvt;
        Fg *= Fg; Fv *= Fv;
        __syncthreads();
    }
    float Eg = (tid + 1 < THREADS) ? sg[tid + 1] : 0.0f;  // carry into segment end
    float Ev = (tid + 1 < THREADS) ? sv[tid + 1] : 0.0f;

    // ---- Recompute with carry: value loss in regs, advantages -> SMEM ----
    const int baseL = tid * SEG;
    const int baseP = baseL + tid;   // == pi(baseL), 21*tid
    float s_vl = 0.0f;
    {
        float g = Eg, V = Ev, vn = vNext;
        #pragma unroll
        for (int i = SEG - 1; i >= 0; --i) {
            float delta = r[i] - v[i] + PPO_GAMMA * vn;
            g = fmaf(PPO_A1,    g, delta);
            V = fmaf(PPO_GAMMA, V, r[i]);
            vn = v[i];
            if (baseL + i < OUT_CHUNK) {
                float d = v[i] - V;
                s_vl = fmaf(d, d, s_vl);
                adv[baseP + i] = g;
            }
        }
    }
    __syncthreads();   // adv visible; sg/sv free for reuse

    // ---- Coalesced float4 pass over probs/probs_old + staged advantages ----
    long long left = (long long)T - s;
    int rem = (left < (long long)OUT_CHUNK) ? (int)left : OUT_CHUNK;
    int nv4 = rem >> 2;
    const float4* p4p  = reinterpret_cast<const float4*>(probs + s);
    const float4* po4p = reinterpret_cast<const float4*>(probs_old + s);

    float s_clip = 0.0f, s_ent = 0.0f;
    for (int k = tid; k < nv4; k += THREADS) {
        float4 p4 = p4p[k];
        float4 o4 = po4p[k];
        float pv[4] = {p4.x, p4.y, p4.z, p4.w};
        float ov[4] = {o4.x, o4.y, o4.z, o4.w};
        int li = 4 * k;
        #pragma unroll
        for (int c = 0; c < 4; ++c) {
            int j = li + c;
            float a = adv[j + j / SEG];
            float ratio = __fdividef(pv[c], ov[c]);
            float cl = fminf(fmaxf(ratio, 1.0f - PPO_EPS), 1.0f + PPO_EPS);
            s_clip += fminf(ratio * a, cl * a);
            s_ent   = fmaf(pv[c], __logf(pv[c] + 1e-5f), s_ent);
        }
    }
    for (int j = (nv4 << 2) + tid; j < rem; j += THREADS) {   // scalar tail
        float p  = probs[s + j];
        float po = probs_old[s + j];
        float a  = adv[j + j / SEG];
        float ratio = __fdividef(p, po);
        float cl = fminf(fmaxf(ratio, 1.0f - PPO_EPS), 1.0f + PPO_EPS);
        s_clip += fminf(ratio * a, cl * a);
        s_ent   = fmaf(p, __logf(p + 1e-5f), s_ent);
    }

    // total = -s_clip + C1*s_vl - C2*s_ent
    float part = -s_clip + PPO_C1 * s_vl - PPO_C2 * s_ent;

    // ---- Block tree reduction (reuse sg) ----
    sg[tid] = part;
    __syncthreads();
    #pragma unroll
    for (int off = THREADS / 2; off > 0; off >>= 1) {
        if (tid < off) sg[tid] += sg[tid + off];
        __syncthreads();
    }

    // ---- Last-block final reduction (deterministic fixed-order sum) ----
    if (tid == 0) {
        g_partials[blockIdx.x] = sg[0];
        __threadfence();
        unsigned int prev = atomicInc(&g_count, gridDim.x - 1);  // wraps to 0
        s_last = (prev == gridDim.x - 1) ? 1u : 0u;
    }
    __syncthreads();
    if (s_last) {
        __threadfence();
        float x = 0.0f;
        for (int i = tid; i < (int)gridDim.x; i += THREADS) x += g_partials[i];
        sg[tid] = x;
        __syncthreads();
        #pragma unroll
        for (int off = THREADS / 2; off > 0; off >>= 1) {
            if (tid < off) sg[tid] += sg[tid + off];
            __syncthreads();
        }
        if (tid == 0) out[0] = sg[0];
    }
}

extern "C" void kernel_launch(void* const* d_in, const int* in_sizes, int n_in,
                              void* d_out, int out_size)
{
    const float* probs     = (const float*)d_in[0];
    const float* probs_old = (const float*)d_in[1];
    const float* rewards   = (const float*)d_in[2];
    const float* values    = (const float*)d_in[3];
    int T = in_sizes[0];

    int nblocks = (T + OUT_CHUNK - 1) / OUT_CHUNK;
    if (nblocks > 4096) nblocks = 4096;   // g_partials capacity (T=2^23 -> 1024)

    ppo_fused<<<nblocks, THREADS>>>(probs, probs_old, rewards, values,
                                    (float*)d_out, T);
}